// round 3
// baseline (speedup 1.0000x reference)
#include <cuda_runtime.h>
#include <math.h>

// LSTM: B=64, T=256, I=512, H=1024  ->  out[b,t,h] fp32
//
// Fused formulation: per timestep t,
//   gates[64,4096] = [h_t | x_t] @ Wp + b     (K = 1024 + 512 = 1536)
// where Wp = [Wh ; Wx] rows-concatenated, columns permuted gate-interleaved
// (dest col 4j+q = gate q of hidden unit j) so each GEMM thread owns the
// complete (i,f,g,o) quadruple and applies the LSTM cell inline.
//
// h is double-buffered across steps (read t&1, write (t+1)&1) so CTAs never
// race on the hidden state within a step. c is read+written by the owning
// thread only. All scratch is static __device__ (no allocations).

#define Bn 64
#define Tn 256
#define In 512
#define Hn 1024
#define Gn 4096              // 4*H
#define Kt (Hn + In)         // 1536 combined K

static __device__ float g_Wp[(size_t)Kt * Gn];   // 24 MB combined permuted weights
static __device__ float g_bp[Gn];                // permuted bias
static __device__ float g_h[2 * Bn * Hn];        // double-buffered hidden state
static __device__ float g_c[Bn * Hn];            // cell state

// ---------------------------------------------------------------------------
// prep: g_Wp[k][4j+q] = (k<Hn ? Wh[k][qH+j] : Wx[k-Hn][qH+j]);  bias permute;
// zero h (both buffers) and c.   Launch: Kt*Gn threads.
// ---------------------------------------------------------------------------
__global__ void prep_kernel(const float* __restrict__ Wx,
                            const float* __restrict__ Wh,
                            const float* __restrict__ b) {
    int idx = blockIdx.x * blockDim.x + threadIdx.x;   // 0 .. Kt*Gn-1
    int k    = idx >> 12;          // 0..1535
    int dcol = idx & (Gn - 1);     // 0..4095
    int j = dcol >> 2;
    int q = dcol & 3;
    int src_col = q * Hn + j;
    float w = (k < Hn) ? Wh[(size_t)k * Gn + src_col]
                       : Wx[(size_t)(k - Hn) * Gn + src_col];
    g_Wp[idx] = w;
    if (k == 0) g_bp[dcol] = b[src_col];
    if (idx < Bn * Hn) {
        g_c[idx] = 0.0f;
        g_h[idx] = 0.0f;
        g_h[Bn * Hn + idx] = 0.0f;
    }
}

// ---------------------------------------------------------------------------
// step t: gates = [h_t | x_t] @ g_Wp + g_bp ; fused LSTM cell.
// grid 128 CTAs (32 permuted cols = 8 hidden units each), 256 threads.
// thread (tx=tid&7, ty=tid>>3): 2 batch rows x 1 hidden unit (4 gate cols).
// ---------------------------------------------------------------------------
__global__ void step_kernel(int t, const float* __restrict__ x,
                            float* __restrict__ out) {
    __shared__ float As[32][64];   // activation tile, transposed [k][m]
    __shared__ float Bs[32][32];   // weight tile [k][n]

    const int tid = threadIdx.x;
    const int tx = tid & 7;
    const int ty = tid >> 3;       // 0..31
    const int colBase = blockIdx.x * 32;

    const float* __restrict__ hin = g_h + (size_t)(t & 1) * (Bn * Hn);
    float* __restrict__ hout      = g_h + (size_t)((t + 1) & 1) * (Bn * Hn);

    float acc[2][4];
#pragma unroll
    for (int i = 0; i < 2; i++)
#pragma unroll
        for (int j = 0; j < 4; j++) acc[i][j] = 0.0f;

    // A-load indices (shared by both phases)
    const int ar0 = tid >> 3;            // 0..31  (rows for l=0)
    const int ak4 = (tid & 7) << 2;      // 0,4,..,28

    for (int k0 = 0; k0 < Kt; k0 += 32) {
        // ---- load A tile: 64 rows x 32 k, 2 float4 per thread ----
#pragma unroll
        for (int l = 0; l < 2; l++) {
            int r = ar0 + l * 32;        // batch row 0..63
            float4 v;
            if (k0 < Hn) {
                v = *(const float4*)(hin + (size_t)r * Hn + k0 + ak4);
            } else {
                v = *(const float4*)(x + ((size_t)r * Tn + t) * In
                                       + (k0 - Hn) + ak4);
            }
            As[ak4 + 0][r] = v.x;
            As[ak4 + 1][r] = v.y;
            As[ak4 + 2][r] = v.z;
            As[ak4 + 3][r] = v.w;
        }
        // ---- load B tile: 32 k x 32 cols, 1 float4 per thread ----
        {
            int kr = tid >> 3;           // 0..31
            int c4 = (tid & 7) << 2;     // 0..28
            *(float4*)&Bs[kr][c4] =
                *(const float4*)(g_Wp + (size_t)(k0 + kr) * Gn + colBase + c4);
        }
        __syncthreads();

#pragma unroll
        for (int kk = 0; kk < 32; kk++) {
            float a0 = As[kk][ty * 2 + 0];
            float a1 = As[kk][ty * 2 + 1];
            float4 bv = *(const float4*)&Bs[kk][tx * 4];
            acc[0][0] = fmaf(a0, bv.x, acc[0][0]);
            acc[0][1] = fmaf(a0, bv.y, acc[0][1]);
            acc[0][2] = fmaf(a0, bv.z, acc[0][2]);
            acc[0][3] = fmaf(a0, bv.w, acc[0][3]);
            acc[1][0] = fmaf(a1, bv.x, acc[1][0]);
            acc[1][1] = fmaf(a1, bv.y, acc[1][1]);
            acc[1][2] = fmaf(a1, bv.z, acc[1][2]);
            acc[1][3] = fmaf(a1, bv.w, acc[1][3]);
        }
        __syncthreads();
    }

    // ---- fused LSTM cell epilogue ----
    const int j = (colBase >> 2) + tx;       // hidden unit 0..1023
    const float* bp = g_bp + colBase + tx * 4;
#pragma unroll
    for (int i = 0; i < 2; i++) {
        int r = ty * 2 + i;                  // batch row 0..63
        float gi = acc[i][0] + bp[0];
        float gf = acc[i][1] + bp[1];
        float gg = acc[i][2] + bp[2];
        float go = acc[i][3] + bp[3];

        float iv = 1.0f / (1.0f + expf(-gi));
        float fv = 1.0f / (1.0f + expf(-gf));
        float gv = tanhf(gg);
        float ov = 1.0f / (1.0f + expf(-go));

        int cidx = r * Hn + j;
        float cn = fv * g_c[cidx] + iv * gv;
        g_c[cidx] = cn;
        float hv = ov * tanhf(cn);
        hout[cidx] = hv;
        out[((size_t)r * Tn + t) * Hn + j] = hv;
    }
}

// ---------------------------------------------------------------------------
extern "C" void kernel_launch(void* const* d_in, const int* in_sizes, int n_in,
                              void* d_out, int out_size) {
    // bind inputs by distinct element count
    const float *x = nullptr, *Wx = nullptr, *Wh = nullptr, *b = nullptr;
    for (int i = 0; i < n_in; i++) {
        switch (in_sizes[i]) {
            case Bn * Tn * In: x  = (const float*)d_in[i]; break;  // 8388608
            case In * Gn:      Wx = (const float*)d_in[i]; break;  // 2097152
            case Hn * Gn:      Wh = (const float*)d_in[i]; break;  // 4194304
            case Gn:           b  = (const float*)d_in[i]; break;  // 4096
        }
    }
    float* out = (float*)d_out;

    prep_kernel<<<(Kt * Gn) / 1024, 1024>>>(Wx, Wh, b);

    for (int t = 0; t < Tn; t++) {
        step_kernel<<<128, 256>>>(t, x, out);
    }
}

// round 4
// speedup vs baseline: 2.6205x; 2.6205x over previous
#include <cuda_runtime.h>
#include <math.h>

// LSTM: B=64, T=256, I=512, H=1024 -> out[b,t,h] fp32
//
// Per step t: gates[64,4096] = [h_t | x_t] @ Wp + b   (K = 1536), fused cell.
// Wp = [Wh ; Wx] rows-concat, cols permuted gate-interleaved (col 4j+q = gate q
// of hidden unit j).
//
// Split-K GEMM: grid (16 col-tiles x 8 K-chunks) = 128 CTAs, BM=64 BN=256,
// K-chunk=192 (6 tiles of BK=32). Partials -> g_part[8][64][4096] (L2-resident).
// Inner product uses fma.rn.f32x2 (2 fp32 FMA / instr). A is stored DUPLICATED
// in smem so LDS.64 yields the {a,a} pair directly (no packing movs).
// cell_kernel reduces the 8 partials + bias and applies the LSTM cell.
// h double-buffered across steps; deterministic (no atomics).

#define Bn 64
#define Tn 256
#define In 512
#define Hn 1024
#define Gn 4096
#define Kt (Hn + In)        // 1536
#define NCH 8               // split-K chunks
#define KCH (Kt / NCH)      // 192
#define BKt 32
#define NTILES (KCH / BKt)  // 6
#define BNt 256

static __device__ float g_Wp[(size_t)Kt * Gn];      // 24 MB permuted weights
static __device__ float g_bp[Gn];
static __device__ float g_h[2 * Bn * Hn];           // double-buffered h
static __device__ float g_c[Bn * Hn];
static __device__ float g_part[(size_t)NCH * Bn * Gn];  // 8 MB split-K partials

// ---------------------------------------------------------------------------
__global__ void prep_kernel(const float* __restrict__ Wx,
                            const float* __restrict__ Wh,
                            const float* __restrict__ b) {
    int idx = blockIdx.x * blockDim.x + threadIdx.x;   // 0 .. Kt*Gn-1
    int k    = idx >> 12;
    int dcol = idx & (Gn - 1);
    int j = dcol >> 2;
    int q = dcol & 3;
    int src_col = q * Hn + j;
    float w = (k < Hn) ? Wh[(size_t)k * Gn + src_col]
                       : Wx[(size_t)(k - Hn) * Gn + src_col];
    g_Wp[idx] = w;
    if (k == 0) g_bp[dcol] = b[src_col];
    if (idx < Bn * Hn) {
        g_c[idx] = 0.0f;
        g_h[idx] = 0.0f;
        g_h[Bn * Hn + idx] = 0.0f;
    }
}

// ---------------------------------------------------------------------------
__device__ __forceinline__ void fma2(unsigned long long& acc,
                                     unsigned long long a2,
                                     unsigned long long b2) {
    asm("fma.rn.f32x2 %0, %1, %2, %0;" : "+l"(acc) : "l"(a2), "l"(b2));
}

__global__ __launch_bounds__(256, 1)
void gemm_kernel(int t, const float* __restrict__ x) {
    // AsD: A tile with every element duplicated: AsD[r][2k], AsD[r][2k+1] = a
    __shared__ float AsD[Bn][2 * BKt];      // 16 KB
    __shared__ float Bs[BKt][BNt];          // 32 KB   (total 48 KB)

    const int tid = threadIdx.x;
    const int tx4 = (tid & 31) * 4;         // col offset within half-tile
    const int ty8 = (tid >> 5) * 8;         // row base (warp id * 8)
    const int colBase = blockIdx.x * BNt;
    const int kBase = blockIdx.y * KCH;
    const float* __restrict__ hin = g_h + (size_t)(t & 1) * (Bn * Hn);

    // A-load indices: 2 float4/thread covering 64 rows x 32 k
    const int ar  = tid >> 3;               // 0..31 (+32 for l=1)
    const int ak4 = (tid & 7) << 2;         // 0,4,...,28
    // B-load indices: 8 float4/thread covering 32 k x 256 cols
    const int bkr = tid >> 6;               // 0..3 (+4*l)
    const int bc4 = (tid & 63) << 2;        // 0..252

    unsigned long long acc2[8][4];
#pragma unroll
    for (int i = 0; i < 8; i++)
#pragma unroll
        for (int j = 0; j < 4; j++) acc2[i][j] = 0ull;

    float4 pa[2], pb[8];

    auto loadT = [&](int k0) {
#pragma unroll
        for (int l = 0; l < 2; l++) {
            int r = ar + l * 32;
            if (k0 < Hn)
                pa[l] = *(const float4*)(hin + (size_t)r * Hn + k0 + ak4);
            else
                pa[l] = *(const float4*)(x + ((size_t)r * Tn + t) * In
                                           + (k0 - Hn) + ak4);
        }
#pragma unroll
        for (int l = 0; l < 8; l++) {
            int kr = bkr + l * 4;
            pb[l] = *(const float4*)(g_Wp + (size_t)(k0 + kr) * Gn
                                          + colBase + bc4);
        }
    };
    auto storeT = [&]() {
#pragma unroll
        for (int l = 0; l < 2; l++) {
            int r = ar + l * 32;
            float4 v = pa[l];
            float4 d0 = make_float4(v.x, v.x, v.y, v.y);
            float4 d1 = make_float4(v.z, v.z, v.w, v.w);
            *(float4*)&AsD[r][2 * ak4]     = d0;
            *(float4*)&AsD[r][2 * ak4 + 4] = d1;
        }
#pragma unroll
        for (int l = 0; l < 8; l++) {
            *(float4*)&Bs[bkr + l * 4][bc4] = pb[l];
        }
    };

    loadT(kBase);
    storeT();
    __syncthreads();

    for (int it = 0; it < NTILES; it++) {
        if (it + 1 < NTILES) loadT(kBase + (it + 1) * BKt);

#pragma unroll
        for (int kk = 0; kk < BKt; kk++) {
            unsigned long long b0 = *(const unsigned long long*)&Bs[kk][tx4];
            unsigned long long b1 = *(const unsigned long long*)&Bs[kk][tx4 + 2];
            unsigned long long b2 = *(const unsigned long long*)&Bs[kk][128 + tx4];
            unsigned long long b3 = *(const unsigned long long*)&Bs[kk][128 + tx4 + 2];
#pragma unroll
            for (int i = 0; i < 8; i++) {
                unsigned long long a2 =
                    *(const unsigned long long*)&AsD[ty8 + i][2 * kk];
                fma2(acc2[i][0], a2, b0);
                fma2(acc2[i][1], a2, b1);
                fma2(acc2[i][2], a2, b2);
                fma2(acc2[i][3], a2, b3);
            }
        }
        __syncthreads();
        if (it + 1 < NTILES) {
            storeT();
            __syncthreads();
        }
    }

    // epilogue: store partials (coalesced float4)
    float* pp = g_part + (size_t)blockIdx.y * (Bn * Gn);
#pragma unroll
    for (int i = 0; i < 8; i++) {
        int r = ty8 + i;
        float lo0, hi0, lo1, hi1;
        asm("mov.b64 {%0, %1}, %2;" : "=f"(lo0), "=f"(hi0) : "l"(acc2[i][0]));
        asm("mov.b64 {%0, %1}, %2;" : "=f"(lo1), "=f"(hi1) : "l"(acc2[i][1]));
        *(float4*)(pp + (size_t)r * Gn + colBase + tx4) =
            make_float4(lo0, hi0, lo1, hi1);
        asm("mov.b64 {%0, %1}, %2;" : "=f"(lo0), "=f"(hi0) : "l"(acc2[i][2]));
        asm("mov.b64 {%0, %1}, %2;" : "=f"(lo1), "=f"(hi1) : "l"(acc2[i][3]));
        *(float4*)(pp + (size_t)r * Gn + colBase + 128 + tx4) =
            make_float4(lo0, hi0, lo1, hi1);
    }
}

// ---------------------------------------------------------------------------
// cell: reduce 8 partials + bias, apply LSTM cell, write h(out) and out.
// 65536 threads: one (batch row r, hidden unit j) each.
// ---------------------------------------------------------------------------
__global__ __launch_bounds__(256)
void cell_kernel(int t, float* __restrict__ out) {
    int gid = blockIdx.x * blockDim.x + threadIdx.x;   // 0..65535
    int r = gid >> 10;
    int j = gid & 1023;
    int col = j << 2;

    float4 s = *(const float4*)(g_part + (size_t)r * Gn + col);
#pragma unroll
    for (int ch = 1; ch < NCH; ch++) {
        float4 p = *(const float4*)(g_part + ((size_t)ch * Bn + r) * Gn + col);
        s.x += p.x; s.y += p.y; s.z += p.z; s.w += p.w;
    }
    float4 bb = *(const float4*)(g_bp + col);
    float gi = s.x + bb.x;
    float gf = s.y + bb.y;
    float gg = s.z + bb.z;
    float go = s.w + bb.w;

    float iv = 1.0f / (1.0f + expf(-gi));
    float fv = 1.0f / (1.0f + expf(-gf));
    float gv = tanhf(gg);
    float ov = 1.0f / (1.0f + expf(-go));

    float cn = fv * g_c[gid] + iv * gv;
    g_c[gid] = cn;
    float hv = ov * tanhf(cn);
    g_h[(size_t)((t + 1) & 1) * (Bn * Hn) + gid] = hv;
    out[((size_t)(r * Tn + t)) * Hn + j] = hv;
}

// ---------------------------------------------------------------------------
extern "C" void kernel_launch(void* const* d_in, const int* in_sizes, int n_in,
                              void* d_out, int out_size) {
    const float *x = nullptr, *Wx = nullptr, *Wh = nullptr, *b = nullptr;
    for (int i = 0; i < n_in; i++) {
        switch (in_sizes[i]) {
            case Bn * Tn * In: x  = (const float*)d_in[i]; break;  // 8388608
            case In * Gn:      Wx = (const float*)d_in[i]; break;  // 2097152
            case Hn * Gn:      Wh = (const float*)d_in[i]; break;  // 4194304
            case Gn:           b  = (const float*)d_in[i]; break;  // 4096
        }
    }
    float* out = (float*)d_out;

    prep_kernel<<<(Kt * Gn) / 1024, 1024>>>(Wx, Wh, b);

    dim3 gg(Gn / BNt, NCH);   // (16, 8) = 128 CTAs
    for (int t = 0; t < Tn; t++) {
        gemm_kernel<<<gg, 256>>>(t, x);
        cell_kernel<<<256, 256>>>(t, out);
    }
}

// round 5
// speedup vs baseline: 2.7924x; 1.0656x over previous
#include <cuda_runtime.h>
#include <math.h>

// LSTM: B=64, T=256, I=512, H=1024 -> out[b,t,h] fp32
//
// Per step t: gates[64,4096] = [h_t | x_t] @ Wp + b (K=1536), fused cell.
// Wp = [Wh;Wx] rows-concat, cols gate-interleaved (col 4j+q = gate q of unit j).
// Split-K: grid (16 col-tiles x 8 K-chunks) = 128 CTAs, BM=64 BN=256,
// K-chunk 192 = 6 tiles of BK=32. Partials -> g_part (8MB, L2-resident).
//
// Inner loop (conflict-free):
//   B: Bs[32][256]; thread cols {2*lane+64c}; LDS.64 reads, consecutive lanes
//      at consecutive 8B -> conflict-free.
//   A: As[32][65] (pad 65 => transpose STS.32 conflict-free); compute reads are
//      warp-uniform broadcast LDS.32; {a,a} pairs built with mov.b64 on the
//      (idle) alu pipe. FMA pipe is the binding constraint by design.

#define Bn 64
#define Tn 256
#define In 512
#define Hn 1024
#define Gn 4096
#define Kt (Hn + In)        // 1536
#define NCH 8               // split-K chunks
#define KCH (Kt / NCH)      // 192
#define BKt 32
#define NTILES (KCH / BKt)  // 6
#define BNt 256

static __device__ float g_Wp[(size_t)Kt * Gn];          // 24 MB permuted weights
static __device__ float g_bp[Gn];
static __device__ float g_h[2 * Bn * Hn];               // double-buffered h
static __device__ float g_c[Bn * Hn];
static __device__ float g_part[(size_t)NCH * Bn * Gn];  // 8 MB partials

// ---------------------------------------------------------------------------
__global__ void prep_kernel(const float* __restrict__ Wx,
                            const float* __restrict__ Wh,
                            const float* __restrict__ b) {
    int idx = blockIdx.x * blockDim.x + threadIdx.x;   // 0 .. Kt*Gn-1
    int k    = idx >> 12;
    int dcol = idx & (Gn - 1);
    int j = dcol >> 2;
    int q = dcol & 3;
    int src_col = q * Hn + j;
    float w = (k < Hn) ? Wh[(size_t)k * Gn + src_col]
                       : Wx[(size_t)(k - Hn) * Gn + src_col];
    g_Wp[idx] = w;
    if (k == 0) g_bp[dcol] = b[src_col];
    if (idx < Bn * Hn) {
        g_c[idx] = 0.0f;
        g_h[idx] = 0.0f;
        g_h[Bn * Hn + idx] = 0.0f;
    }
}

// ---------------------------------------------------------------------------
__device__ __forceinline__ void fma2(unsigned long long& acc,
                                     unsigned long long a2,
                                     unsigned long long b2) {
    asm("fma.rn.f32x2 %0, %1, %2, %0;" : "+l"(acc) : "l"(a2), "l"(b2));
}
__device__ __forceinline__ unsigned long long dup2(float v) {
    unsigned long long r;
    asm("mov.b64 %0, {%1, %1};" : "=l"(r) : "f"(v));
    return r;
}

__global__ __launch_bounds__(256, 1)
void gemm_kernel(int t, const float* __restrict__ x) {
    __shared__ float As[BKt][65];     // padded: transpose-store conflict-free
    __shared__ float Bs[BKt][BNt];    // 32 KB

    const int tid  = threadIdx.x;
    const int lane = tid & 31;
    const int warp = tid >> 5;
    const int ty8  = warp * 8;              // 8 rows per warp
    const int colBase = blockIdx.x * BNt;
    const int kBase   = blockIdx.y * KCH;
    const float* __restrict__ hin = g_h + (size_t)(t & 1) * (Bn * Hn);

    // A-load: 2 float4/thread covering 64 rows x 32 k (row-major from gmem)
    const int ar  = tid >> 3;               // 0..31 (+32)
    const int ak4 = (tid & 7) << 2;         // 0,4,...,28
    // B-load: 8 float4/thread covering 32 k x 256 cols
    const int bkr = tid >> 6;               // 0..3 (+4l)
    const int bc4 = (tid & 63) << 2;        // 0..252

    unsigned long long acc2[8][4];          // 8 rows x 4 col-pairs
#pragma unroll
    for (int i = 0; i < 8; i++)
#pragma unroll
        for (int c = 0; c < 4; c++) acc2[i][c] = 0ull;

    float4 pa[2], pb[8];

    auto loadT = [&](int k0) {
#pragma unroll
        for (int l = 0; l < 2; l++) {
            int r = ar + l * 32;
            if (k0 < Hn)
                pa[l] = *(const float4*)(hin + (size_t)r * Hn + k0 + ak4);
            else
                pa[l] = *(const float4*)(x + ((size_t)r * Tn + t) * In
                                           + (k0 - Hn) + ak4);
        }
#pragma unroll
        for (int l = 0; l < 8; l++)
            pb[l] = *(const float4*)(g_Wp + (size_t)(k0 + bkr + l * 4) * Gn
                                          + colBase + bc4);
    };
    auto storeT = [&]() {
#pragma unroll
        for (int l = 0; l < 2; l++) {
            int r = ar + l * 32;
            As[ak4 + 0][r] = pa[l].x;       // conflict-free: bank = ak4+c+ar
            As[ak4 + 1][r] = pa[l].y;
            As[ak4 + 2][r] = pa[l].z;
            As[ak4 + 3][r] = pa[l].w;
        }
#pragma unroll
        for (int l = 0; l < 8; l++)
            *(float4*)&Bs[bkr + l * 4][bc4] = pb[l];
    };

    loadT(kBase);
    storeT();
    __syncthreads();

    for (int it = 0; it < NTILES; it++) {
        if (it + 1 < NTILES) loadT(kBase + (it + 1) * BKt);

#pragma unroll
        for (int kk = 0; kk < BKt; kk++) {
            unsigned long long b2[4];
#pragma unroll
            for (int c = 0; c < 4; c++)
                b2[c] = *(const unsigned long long*)&Bs[kk][2 * lane + 64 * c];
#pragma unroll
            for (int i = 0; i < 8; i++) {
                unsigned long long a2 = dup2(As[kk][ty8 + i]);  // bcast + pack
                fma2(acc2[i][0], a2, b2[0]);
                fma2(acc2[i][1], a2, b2[1]);
                fma2(acc2[i][2], a2, b2[2]);
                fma2(acc2[i][3], a2, b2[3]);
            }
        }
        __syncthreads();
        if (it + 1 < NTILES) {
            storeT();
            __syncthreads();
        }
    }

    // epilogue: store partials, coalesced STG.64 (lanes at consecutive 8B)
    float* pp = g_part + (size_t)blockIdx.y * (Bn * Gn);
#pragma unroll
    for (int i = 0; i < 8; i++) {
        size_t rowOff = (size_t)(ty8 + i) * Gn + colBase + 2 * lane;
#pragma unroll
        for (int c = 0; c < 4; c++)
            *(float2*)(pp + rowOff + 64 * c) = *(float2*)&acc2[i][c];
    }
}

// ---------------------------------------------------------------------------
// cell: reduce 8 partials + bias, LSTM cell, write h(next) and out.
// ---------------------------------------------------------------------------
__global__ __launch_bounds__(256)
void cell_kernel(int t, float* __restrict__ out) {
    int gid = blockIdx.x * blockDim.x + threadIdx.x;   // 0..65535
    int r = gid >> 10;
    int j = gid & 1023;
    int col = j << 2;

    float4 s = *(const float4*)(g_part + (size_t)r * Gn + col);
#pragma unroll
    for (int ch = 1; ch < NCH; ch++) {
        float4 p = *(const float4*)(g_part + ((size_t)ch * Bn + r) * Gn + col);
        s.x += p.x; s.y += p.y; s.z += p.z; s.w += p.w;
    }
    float4 bb = *(const float4*)(g_bp + col);
    float gi = s.x + bb.x;
    float gf = s.y + bb.y;
    float gg = s.z + bb.z;
    float go = s.w + bb.w;

    float iv = 1.0f / (1.0f + expf(-gi));
    float fv = 1.0f / (1.0f + expf(-gf));
    float gv = tanhf(gg);
    float ov = 1.0f / (1.0f + expf(-go));

    float cn = fv * g_c[gid] + iv * gv;
    g_c[gid] = cn;
    float hv = ov * tanhf(cn);
    g_h[(size_t)((t + 1) & 1) * (Bn * Hn) + gid] = hv;
    out[((size_t)(r * Tn + t)) * Hn + j] = hv;
}

// ---------------------------------------------------------------------------
extern "C" void kernel_launch(void* const* d_in, const int* in_sizes, int n_in,
                              void* d_out, int out_size) {
    const float *x = nullptr, *Wx = nullptr, *Wh = nullptr, *b = nullptr;
    for (int i = 0; i < n_in; i++) {
        switch (in_sizes[i]) {
            case Bn * Tn * In: x  = (const float*)d_in[i]; break;  // 8388608
            case In * Gn:      Wx = (const float*)d_in[i]; break;  // 2097152
            case Hn * Gn:      Wh = (const float*)d_in[i]; break;  // 4194304
            case Gn:           b  = (const float*)d_in[i]; break;  // 4096
        }
    }
    float* out = (float*)d_out;

    prep_kernel<<<(Kt * Gn) / 1024, 1024>>>(Wx, Wh, b);

    dim3 gg(Gn / BNt, NCH);   // (16, 8) = 128 CTAs
    for (int t = 0; t < Tn; t++) {
        gemm_kernel<<<gg, 256>>>(t, x);
        cell_kernel<<<256, 256>>>(t, out);
    }
}

// round 7
// speedup vs baseline: 5.0033x; 1.7918x over previous
#include <cuda_runtime.h>
#include <cuda_bf16.h>
#include <stdint.h>
#include <math.h>

// LSTM: B=64, T=256, I=512, H=1024 -> out[b,t,h] fp32
//
// Per step t: gates^T D[gc, r] = sum_k Wt[gc][k] * act[r][k],  K = 1536,
// Wt = [Wh;Wx]^T gate-interleaved (gc = 4j+q), act = [h_t | x_t].
//
// Precision: bf16 2-term split (hi+lo) of W and act; 3 tensor-core products
// (hi*hi + hi*lo + lo*hi) accumulated in fp32 => rel err ~1e-4.
//
// Tensor path: mma.sync.m16n8k16.bf16 (compute_100-legal; HMMA on Blackwell),
// ldmatrix fragments from SW128-swizzled smem, cp.async double-buffered
// stages. Grid: 32 M-tiles (128 gc) x 4 K-splits (384) = 128 CTAs, 8 warps,
// warp tile 32gc x 32n. Partials -> g_part[ch][gc][r]; cell_kernel reduces,
// applies LSTM cell, writes out + re-split h.

#define Bn 64
#define Tn 256
#define In 512
#define Hn 1024
#define Gn 4096
#define Kt 1536
#define NCH 4
#define KCH 384
#define BK 64
#define NCHUNK 6

// stage layout (bytes): WH 0..16K, WL 16K..32K, AH 32K..40K, AL 40K..48K
#define ST_WH 0
#define ST_WL 16384
#define ST_AH 32768
#define ST_AL 40960
#define STAGE_BYTES 49152
#define SMEM_TOTAL (2 * STAGE_BYTES)

#define SWZ(o) ((o) ^ (((o) >> 3) & 0x70))

static __device__ __nv_bfloat16 g_Whi[(size_t)Gn * Kt];
static __device__ __nv_bfloat16 g_Wlo[(size_t)Gn * Kt];
static __device__ __nv_bfloat16 g_xhi[(size_t)Bn * Tn * In];
static __device__ __nv_bfloat16 g_xlo[(size_t)Bn * Tn * In];
static __device__ __nv_bfloat16 g_hhi[Bn * Hn];
static __device__ __nv_bfloat16 g_hlo[Bn * Hn];
static __device__ float g_c[Bn * Hn];
static __device__ float g_bp[Gn];
static __device__ float g_part[(size_t)NCH * Gn * Bn];   // [ch][gc][r] 4 MB

// ---------------------------------------------------------------------------
__device__ __forceinline__ uint32_t smem_u32(const void* p) {
    uint32_t a;
    asm("{ .reg .u64 t; cvta.to.shared.u64 t, %1; cvt.u32.u64 %0, t; }"
        : "=r"(a) : "l"(p));
    return a;
}
__device__ __forceinline__ void cpa16(uint32_t dst, const void* src) {
    asm volatile("cp.async.cg.shared.global [%0], [%1], 16;"
                 :: "r"(dst), "l"(src));
}
#define CP_COMMIT() asm volatile("cp.async.commit_group;" ::: "memory")
#define CP_WAIT(n)  asm volatile("cp.async.wait_group %0;" :: "n"(n) : "memory")

__device__ __forceinline__ void ldm_x4(uint32_t a, uint32_t r[4]) {
    asm volatile("ldmatrix.sync.aligned.m8n8.x4.shared.b16 {%0,%1,%2,%3}, [%4];"
                 : "=r"(r[0]), "=r"(r[1]), "=r"(r[2]), "=r"(r[3]) : "r"(a));
}
__device__ __forceinline__ void mma16816(float acc[4], const uint32_t a[4],
                                         uint32_t b0, uint32_t b1) {
    asm volatile(
        "mma.sync.aligned.m16n8k16.row.col.f32.bf16.bf16.f32 "
        "{%0,%1,%2,%3}, {%4,%5,%6,%7}, {%8,%9}, {%0,%1,%2,%3};"
        : "+f"(acc[0]), "+f"(acc[1]), "+f"(acc[2]), "+f"(acc[3])
        : "r"(a[0]), "r"(a[1]), "r"(a[2]), "r"(a[3]), "r"(b0), "r"(b1));
}

// ---------------------------------------------------------------------------
// wprep: Wt hi/lo [4096][1536] bf16 gate-interleaved; bias permute.
// ---------------------------------------------------------------------------
__global__ void wprep_kernel(const float* __restrict__ Wx,
                             const float* __restrict__ Wh,
                             const float* __restrict__ b) {
    int gc = blockIdx.x;
    int k  = blockIdx.y * 256 + threadIdx.x;
    int j = gc >> 2, q = gc & 3;
    int src = q * Hn + j;
    float w = (k < Hn) ? Wh[(size_t)k * Gn + src]
                       : Wx[(size_t)(k - Hn) * Gn + src];
    __nv_bfloat16 hi = __float2bfloat16(w);
    g_Whi[(size_t)gc * Kt + k] = hi;
    g_Wlo[(size_t)gc * Kt + k] = __float2bfloat16(w - __bfloat162float(hi));
    if (k == 0) g_bp[gc] = b[src];
}

// ---------------------------------------------------------------------------
__global__ void xprep_kernel(const float* __restrict__ x) {
    int idx = blockIdx.x * 1024 + threadIdx.x;
    float v = x[idx];
    __nv_bfloat16 hi = __float2bfloat16(v);
    g_xhi[idx] = hi;
    g_xlo[idx] = __float2bfloat16(v - __bfloat162float(hi));
    if (idx < Bn * Hn) {
        g_c[idx] = 0.0f;
        g_hhi[idx] = __float2bfloat16(0.0f);
        g_hlo[idx] = __float2bfloat16(0.0f);
    }
}

// ---------------------------------------------------------------------------
// gemm: D[128 gc, 64 r] per (Mtile, ch). 8 warps (4 m-rows x 2 n-cols),
// warp tile 32gc x 32n, k-steps of 16 within 6 BK=64 cp.async stages.
// ---------------------------------------------------------------------------
__global__ __launch_bounds__(256, 1)
void gemm_kernel(int t) {
    extern __shared__ char smem[];
    const uint32_t sb = smem_u32(smem);

    const int tid   = threadIdx.x;
    const int lane  = tid & 31;
    const int warp  = tid >> 5;
    const int wr    = warp & 3;          // m block: 32 gc
    const int wc    = warp >> 2;         // n block: 32 batch
    const int Mtile = blockIdx.x;
    const int ch    = blockIdx.y;
    const int kBase = ch * KCH;
    const float* dummy;

    // ---- async stage loader (cp.async 16B) ----
    auto load_stage = [&](int c) {
        const uint32_t st = sb + (uint32_t)(c & 1) * STAGE_BYTES;
        const int k0 = kBase + c * BK;
        // W tiles: 128 rows x 64 bf16; 1024 ops hi + 1024 lo / 256 thr
#pragma unroll
        for (int i = 0; i < 4; i++) {
            int l = tid + 256 * i;
            int row = l >> 3;
            int kq = (l & 7) << 3;                   // bf16 idx, 8 per 16B
            uint32_t off = SWZ((uint32_t)(row * 128 + kq * 2));
            size_t ga = (size_t)(Mtile * 128 + row) * Kt + k0 + kq;
            cpa16(st + ST_WH + off, g_Whi + ga);
            cpa16(st + ST_WL + off, g_Wlo + ga);
        }
        // act tiles: 64 rows x 64 bf16
#pragma unroll
        for (int i = 0; i < 2; i++) {
            int l = tid + 256 * i;
            int row = l >> 3;                        // batch 0..63
            int kq = (l & 7) << 3;
            uint32_t off = SWZ((uint32_t)(row * 128 + kq * 2));
            int k = k0 + kq;
            const __nv_bfloat16 *ph, *pl;
            if (k < Hn) {
                ph = g_hhi + row * Hn + k;
                pl = g_hlo + row * Hn + k;
            } else {
                size_t xo = ((size_t)row * Tn + t) * In + (k - Hn);
                ph = g_xhi + xo;
                pl = g_xlo + xo;
            }
            cpa16(st + ST_AH + off, ph);
            cpa16(st + ST_AL + off, pl);
        }
        CP_COMMIT();
    };

    float acc[2][4][4];
#pragma unroll
    for (int mt = 0; mt < 2; mt++)
#pragma unroll
        for (int nt = 0; nt < 4; nt++)
#pragma unroll
            for (int e = 0; e < 4; e++) acc[mt][nt][e] = 0.0f;

    // ldmatrix lane indices
    const int lm_m = lane >> 3;          // matrix id 0..3
    const int lm_r = lane & 7;           // row within matrix

    load_stage(0);

    for (int c = 0; c < NCHUNK; c++) {
        if (c + 1 < NCHUNK) load_stage(c + 1);
        if (c + 1 < NCHUNK) { CP_WAIT(1); } else { CP_WAIT(0); }
        __syncthreads();

        const uint32_t st = sb + (uint32_t)(c & 1) * STAGE_BYTES;

#pragma unroll
        for (int ks = 0; ks < 4; ks++) {
            const int kc = ks * 16;
            uint32_t ah[2][4], al[2][4];
            // A frags: rows wr*32 + mt*16 + (m&1)*8 + r ; k = kc + (m>>1)*8
#pragma unroll
            for (int mt = 0; mt < 2; mt++) {
                int row = wr * 32 + mt * 16 + (lm_m & 1) * 8 + lm_r;
                int kcol = kc + (lm_m >> 1) * 8;
                uint32_t off = SWZ((uint32_t)(row * 128 + kcol * 2));
                ldm_x4(st + ST_WH + off, ah[mt]);
                ldm_x4(st + ST_WL + off, al[mt]);
            }
            uint32_t bh[4][2], bl[4][2];
            // B frags: 2 n-groups per ldmatrix.x4
            //   matrix m: n = wc*32 + np*16 + (m>>1)*8 + r ; k = kc + (m&1)*8
#pragma unroll
            for (int np = 0; np < 2; np++) {
                int nrow = wc * 32 + np * 16 + (lm_m >> 1) * 8 + lm_r;
                int kcol = kc + (lm_m & 1) * 8;
                uint32_t off = SWZ((uint32_t)(nrow * 128 + kcol * 2));
                uint32_t rh[4], rl[4];
                ldm_x4(st + ST_AH + off, rh);
                ldm_x4(st + ST_AL + off, rl);
                bh[2 * np][0] = rh[0]; bh[2 * np][1] = rh[1];
                bh[2 * np + 1][0] = rh[2]; bh[2 * np + 1][1] = rh[3];
                bl[2 * np][0] = rl[0]; bl[2 * np][1] = rl[1];
                bl[2 * np + 1][0] = rl[2]; bl[2 * np + 1][1] = rl[3];
            }
#pragma unroll
            for (int mt = 0; mt < 2; mt++)
#pragma unroll
                for (int nt = 0; nt < 4; nt++) {
                    mma16816(acc[mt][nt], ah[mt], bh[nt][0], bh[nt][1]);
                    mma16816(acc[mt][nt], ah[mt], bl[nt][0], bl[nt][1]);
                    mma16816(acc[mt][nt], al[mt], bh[nt][0], bh[nt][1]);
                }
        }
        __syncthreads();
    }

    // epilogue: D frag lane map: g=lane>>2, tq=lane&3:
    //   d0,d1 = D[g][2tq],D[g][2tq+1]; d2,d3 = D[g+8][...]
    const int dg = lane >> 2;
    const int dt = lane & 3;
#pragma unroll
    for (int mt = 0; mt < 2; mt++)
#pragma unroll
        for (int nt = 0; nt < 4; nt++) {
            int gc0 = Mtile * 128 + wr * 32 + mt * 16 + dg;
            int r0  = wc * 32 + nt * 8 + 2 * dt;
            float* p0 = g_part + ((size_t)ch * Gn + gc0) * Bn + r0;
            *(float2*)p0 = make_float2(acc[mt][nt][0], acc[mt][nt][1]);
            float* p1 = g_part + ((size_t)ch * Gn + gc0 + 8) * Bn + r0;
            *(float2*)p1 = make_float2(acc[mt][nt][2], acc[mt][nt][3]);
        }
    (void)dummy;
}

// ---------------------------------------------------------------------------
// cell: reduce NCH partials + bias, LSTM cell, out + h re-split.
// ---------------------------------------------------------------------------
__global__ __launch_bounds__(256)
void cell_kernel(int t, float* __restrict__ out) {
    int jj = threadIdx.x >> 6;
    int r  = threadIdx.x & 63;
    int j  = blockIdx.x * 4 + jj;

    float g[4];
#pragma unroll
    for (int q = 0; q < 4; q++) {
        int gc = 4 * j + q;
        float s = 0.0f;
#pragma unroll
        for (int c2 = 0; c2 < NCH; c2++)
            s += g_part[((size_t)c2 * Gn + gc) * Bn + r];
        g[q] = s + g_bp[gc];
    }
    float iv = 1.0f / (1.0f + expf(-g[0]));
    float fv = 1.0f / (1.0f + expf(-g[1]));
    float gv = tanhf(g[2]);
    float ov = 1.0f / (1.0f + expf(-g[3]));

    int ci = r * Hn + j;
    float cn = fv * g_c[ci] + iv * gv;
    g_c[ci] = cn;
    float hv = ov * tanhf(cn);

    __nv_bfloat16 hh = __float2bfloat16(hv);
    g_hhi[ci] = hh;
    g_hlo[ci] = __float2bfloat16(hv - __bfloat162float(hh));
    out[((size_t)r * Tn + t) * Hn + j] = hv;
}

// ---------------------------------------------------------------------------
extern "C" void kernel_launch(void* const* d_in, const int* in_sizes, int n_in,
                              void* d_out, int out_size) {
    const float *x = nullptr, *Wx = nullptr, *Wh = nullptr, *b = nullptr;
    for (int i = 0; i < n_in; i++) {
        switch (in_sizes[i]) {
            case Bn * Tn * In: x  = (const float*)d_in[i]; break;  // 8388608
            case In * Gn:      Wx = (const float*)d_in[i]; break;  // 2097152
            case Hn * Gn:      Wh = (const float*)d_in[i]; break;  // 4194304
            case Gn:           b  = (const float*)d_in[i]; break;  // 4096
        }
    }
    float* out = (float*)d_out;

    (void)cudaFuncSetAttribute(gemm_kernel,
                               cudaFuncAttributeMaxDynamicSharedMemorySize,
                               SMEM_TOTAL);

    wprep_kernel<<<dim3(Gn, 6), 256>>>(Wx, Wh, b);
    xprep_kernel<<<8192, 1024>>>(x);

    for (int t = 0; t < Tn; t++) {
        gemm_kernel<<<dim3(32, NCH), 256, SMEM_TOTAL>>>(t);
        cell_kernel<<<256, 256>>>(t, out);
    }
}